// round 10
// baseline (speedup 1.0000x reference)
#include <cuda_runtime.h>
#include <cuda_fp16.h>
#include <cstdint>
#include <cstddef>

// B=32, T=64, H=1024. fp16 operands / fp32 accum everywhere.
#define HD 1024
#define BB 32
#define TT 64
#define G4 4096
#define BT 2048

// ---------------- static device buffers ----------------
__device__ __align__(1024) __half g_Xa   [BT * 2048];
__device__ __align__(1024) __half g_Xm   [BT * 2048];
__device__ __align__(1024) __half g_Wih1a[G4 * 2048];
__device__ __align__(1024) __half g_Wih1m[G4 * 2048];
__device__ __align__(1024) __half g_Whh1a[G4 * HD];
__device__ __align__(1024) __half g_Whh1m[G4 * HD];
__device__ __align__(1024) __half g_Wih2a[G4 * HD];
__device__ __align__(1024) __half g_Wih2m[G4 * HD];
__device__ __align__(1024) __half g_Whh2a[G4 * HD];
__device__ __align__(1024) __half g_Whh2m[G4 * HD];
__device__ __align__(1024) __half g_Wg   [HD * 2048];
__device__ __align__(1024) __half g_Wa   [HD * HD];
__device__ __align__(1024) __half g_Wm   [HD * HD];

__device__ __align__(1024) float  g_X1a[(size_t)BT * G4];
__device__ __align__(1024) float  g_X1m[(size_t)BT * G4];
__device__ float g_bias1a[G4], g_bias1m[G4], g_bias2a[G4], g_bias2m[G4];

__device__ __align__(1024) __half g_h1a[2][BB * HD];
__device__ __align__(1024) __half g_h1m[2][BB * HD];
__device__ __align__(1024) __half g_h2a[BB * HD];
__device__ __align__(1024) __half g_h2m[BB * HD];
__device__ __align__(1024) float  g_c1a[BB * HD], g_c1m[BB * HD];
__device__ __align__(1024) float  g_c2a[BB * HD], g_c2m[BB * HD];
__device__ __align__(1024) float  g_part2a[BB * G4], g_part2m[BB * G4];

__device__ __align__(1024) __half g_Hcat[BT * 2048];
__device__ __align__(1024) float  g_Sa[BT * HD], g_Sm[BT * HD], g_Gl[BT * HD];

// device-wide barrier state for the persistent sequential kernel
__device__ int          g_bar_count = 0;
__device__ volatile int g_bar_gen   = 0;

// ---------------- helpers ----------------
__device__ __forceinline__ float sigf(float x) { return 1.f / (1.f + expf(-x)); }

__device__ __forceinline__ void cp8(void* s, const void* g) {
    uint32_t sa = (uint32_t)__cvta_generic_to_shared(s);
    asm volatile("cp.async.ca.shared.global [%0], [%1], 8;" :: "r"(sa), "l"(g));
}

__device__ __forceinline__ void mma16816(float* d, const uint32_t* a, const uint32_t* b) {
    asm volatile(
        "mma.sync.aligned.m16n8k16.row.col.f32.f16.f16.f32 "
        "{%0,%1,%2,%3}, {%4,%5,%6,%7}, {%8,%9}, {%0,%1,%2,%3};"
        : "+f"(d[0]), "+f"(d[1]), "+f"(d[2]), "+f"(d[3])
        : "r"(a[0]), "r"(a[1]), "r"(a[2]), "r"(a[3]), "r"(b[0]), "r"(b[1]));
}

// exact tail-laddered wait: group kt must be complete
__device__ __forceinline__ void wait_tail(int kt, int KT) {
    if (kt + 3 < KT)      asm volatile("cp.async.wait_group 3;" ::: "memory");
    else if (kt + 2 < KT) asm volatile("cp.async.wait_group 2;" ::: "memory");
    else if (kt + 1 < KT) asm volatile("cp.async.wait_group 1;" ::: "memory");
    else                  asm volatile("cp.async.wait_group 0;" ::: "memory");
}

// all-CTA barrier (all CTAs resident: grid=128 <= 148 SMs), tight spin
__device__ __forceinline__ void gsync(int nblocks) {
    __syncthreads();
    if (threadIdx.x == 0) {
        int gen = g_bar_gen;
        __threadfence();
        if (atomicAdd(&g_bar_count, 1) == nblocks - 1) {
            g_bar_count = 0;
            __threadfence();
            g_bar_gen = gen + 1;
        } else {
            while (g_bar_gen == gen) { }
        }
        __threadfence();
    }
    __syncthreads();
}

// ---------------- big GEMM: 4-stage cp.async pipeline -----------------------
// C[128,128] tile += A[128,K] @ Bw[128 rows,K]^T. 256 thr, warps 2x4, BK=32.
#define BKC 32
#define SK  40
#define SKW 20
#define BIG_STAGE_BYTES (256 * SK * 2)          // (128 A rows + 128 B rows) * 40 * 2B = 20480
#define BIG_DYN (4 * BIG_STAGE_BYTES)           // 81920

__global__ void __launch_bounds__(256) gemm_big(int which)
{
    extern __shared__ __align__(16) char dyn[];

    const __half *A, *Bw;
    float* C;
    const float* bias = nullptr;
    int lda, ldb, K, ldc;
    const int n0 = blockIdx.x * 128, m0 = blockIdx.y * 128;
    switch (which) {
        case 0: A = g_Xa;        lda = 2048; Bw = g_Wih1a; ldb = 2048; K = 2048; C = g_X1a; ldc = G4; bias = g_bias1a; break;
        case 1: A = g_Xm;        lda = 2048; Bw = g_Wih1m; ldb = 2048; K = 2048; C = g_X1m; ldc = G4; bias = g_bias1m; break;
        case 2: A = g_Hcat;      lda = 2048; Bw = g_Wa;    ldb = HD;   K = HD;   C = g_Sa;  ldc = HD; break;
        case 3: A = g_Hcat + HD; lda = 2048; Bw = g_Wm;    ldb = HD;   K = HD;   C = g_Sm;  ldc = HD; break;
        default:A = g_Hcat;      lda = 2048; Bw = g_Wg;    ldb = 2048; K = 2048; C = g_Gl;  ldc = HD; break;
    }
    A += (size_t)m0 * lda;

    const int tid  = threadIdx.x;
    const int warp = tid >> 5, lane = tid & 31;
    const int wm = warp >> 2, wn = warp & 3;
    const int grp = lane >> 2, tig = lane & 3;

    auto load_tile = [&](int kt) {
        char* st = dyn + (kt & 3) * BIG_STAGE_BYTES;
        __half* sa = (__half*)st;
        __half* sb = (__half*)(st + 128 * SK * 2);
        const __half* Ag = A + kt * BKC;
        const __half* Bg = Bw + kt * BKC;
        for (int idx = tid; idx < 2048; idx += 256) {
            int r = (idx >> 3) & 127, c = idx & 7;
            if (idx < 1024)
                cp8(sa + r * SK + c * 4, Ag + (size_t)r * lda + c * 4);
            else
                cp8(sb + r * SK + c * 4, Bg + (size_t)(n0 + r) * ldb + c * 4);
        }
        asm volatile("cp.async.commit_group;" ::: "memory");
    };

    float acc[16][4] = {};
    const int KT = K / BKC;
    load_tile(0); load_tile(1); load_tile(2);

    for (int kt = 0; kt < KT; kt++) {
        if (kt + 3 < KT) load_tile(kt + 3);
        wait_tail(kt, KT);
        __syncthreads();
        char* st = dyn + (kt & 3) * BIG_STAGE_BYTES;
        const uint32_t* wA = (const uint32_t*)st;
        const uint32_t* wB = (const uint32_t*)(st + 128 * SK * 2);
        #pragma unroll
        for (int kk = 0; kk < 2; kk++) {
            uint32_t af[4][4], bf[4][2];
            #pragma unroll
            for (int mi = 0; mi < 4; mi++) {
                int r = wm * 64 + mi * 16 + grp;
                int base = r * SKW + kk * 8 + tig;
                af[mi][0] = wA[base];
                af[mi][1] = wA[base + 8 * SKW];
                af[mi][2] = wA[base + 4];
                af[mi][3] = wA[base + 8 * SKW + 4];
            }
            #pragma unroll
            for (int ni = 0; ni < 4; ni++) {
                int rb = wn * 32 + ni * 8 + grp;
                int base = rb * SKW + kk * 8 + tig;
                bf[ni][0] = wB[base];
                bf[ni][1] = wB[base + 4];
            }
            #pragma unroll
            for (int mi = 0; mi < 4; mi++)
                #pragma unroll
                for (int ni = 0; ni < 4; ni++)
                    mma16816(acc[mi * 4 + ni], af[mi], bf[ni]);
        }
        __syncthreads();
    }

    #pragma unroll
    for (int mi = 0; mi < 4; mi++)
        #pragma unroll
        for (int ni = 0; ni < 4; ni++) {
            int r = m0 + wm * 64 + mi * 16 + grp;
            int c = n0 + wn * 32 + ni * 8 + tig * 2;
            float b0 = 0.f, b1 = 0.f;
            if (bias) { b0 = bias[c]; b1 = bias[c + 1]; }
            float* p = C + (size_t)r * ldc + c;
            p[0] = acc[mi * 4 + ni][0] + b0;
            p[1] = acc[mi * 4 + ni][1] + b1;
            p = C + (size_t)(r + 8) * ldc + c;
            p[0] = acc[mi * 4 + ni][2] + b0;
            p[1] = acc[mi * 4 + ni][3] + b1;
        }
}

// ---------------- sequential-core GEMM: 4-stage, BM=32, BN {128,64}, BK=64 --
// weight row = gate*1024 + u0 + unit; gate = r>>GS, unit = r&((1<<GS)-1).
#define BK2  64
#define SK2  72
#define SK2W 36
#define SEQ_STAGE_BYTES (160 * SK2 * 2)         // (32 A + 128 B rows) * 72 * 2B = 23040
#define SEQ_DYN (4 * SEQ_STAGE_BYTES)           // 92160
#define SEQ_CTAS 128

template<int BN, int NI, int GS>
__device__ __forceinline__ void run_gemm_seq(
    const __half* __restrict__ A,
    const __half* __restrict__ Bw, int u0,
    char* dyn, float (*acc)[4])
{
    const int tid  = threadIdx.x;
    const int warp = tid >> 5, lane = tid & 31;
    const int wm = warp >> 2, wn = warp & 3;
    const int grp = lane >> 2, tig = lane & 3;

    constexpr int TOT = 512 + BN * 16;

    auto load_tile = [&](int kt) {
        const int k0 = kt * BK2;
        char* st = dyn + (kt & 3) * SEQ_STAGE_BYTES;
        __half* sa = (__half*)st;
        __half* sb = (__half*)(st + 32 * SK2 * 2);
        for (int idx = tid; idx < TOT; idx += 256) {
            if (idx < 512) {
                int r = idx >> 4, c = idx & 15;
                cp8(sa + r * SK2 + c * 4, A + (size_t)r * HD + k0 + c * 4);
            } else {
                int j = idx - 512;
                int r = j >> 4, c = j & 15;
                int wr = ((r >> GS) << 10) + u0 + (r & ((1 << GS) - 1));
                cp8(sb + r * SK2 + c * 4, Bw + (size_t)wr * HD + k0 + c * 4);
            }
        }
        asm volatile("cp.async.commit_group;" ::: "memory");
    };

    const int KT = HD / BK2;   // 16
    load_tile(0); load_tile(1); load_tile(2);

    for (int kt = 0; kt < KT; kt++) {
        if (kt + 3 < KT) load_tile(kt + 3);
        wait_tail(kt, KT);
        __syncthreads();
        char* st = dyn + (kt & 3) * SEQ_STAGE_BYTES;
        const uint32_t* wA = (const uint32_t*)st;
        const uint32_t* wB = (const uint32_t*)(st + 32 * SK2 * 2);
        #pragma unroll
        for (int kk = 0; kk < 4; kk++) {
            uint32_t af[4], bf[NI][2];
            {
                int r = wm * 16 + grp;
                int base = r * SK2W + kk * 8 + tig;
                af[0] = wA[base];
                af[1] = wA[base + 8 * SK2W];
                af[2] = wA[base + 4];
                af[3] = wA[base + 8 * SK2W + 4];
            }
            #pragma unroll
            for (int ni = 0; ni < NI; ni++) {
                int rb = wn * (NI * 8) + ni * 8 + grp;
                int base = rb * SK2W + kk * 8 + tig;
                bf[ni][0] = wB[base];
                bf[ni][1] = wB[base + 4];
            }
            #pragma unroll
            for (int ni = 0; ni < NI; ni++)
                mma16816(acc[ni], af, bf[ni]);
        }
        __syncthreads();
    }
}

template<int BN, int NI>
__device__ __forceinline__ void seq_store_sC(float* sC, float (*acc)[4])
{
    const int warp = threadIdx.x >> 5, lane = threadIdx.x & 31;
    const int wm = warp >> 2, wn = warp & 3, grp = lane >> 2, tig = lane & 3;
    #pragma unroll
    for (int ni = 0; ni < NI; ni++) {
        int r = wm * 16 + grp, c = wn * (NI * 8) + ni * 8 + tig * 2;
        sC[r * BN + c]           = acc[ni][0];  sC[r * BN + c + 1]       = acc[ni][1];
        sC[(r + 8) * BN + c]     = acc[ni][2];  sC[(r + 8) * BN + c + 1] = acc[ni][3];
    }
}

// ---------------- persistent sequential kernel (grid = 128 CTAs) ------------
__global__ void __launch_bounds__(256) seq_kernel()
{
    extern __shared__ __align__(16) char dyn[];
    float* sC = (float*)dyn;

    const int bx   = blockIdx.x;
    const int cid  = bx >> 5, u0  = (bx & 31) << 5;   // phase 1
    const int cell = bx >> 6, u0p = (bx & 63) << 4;   // phase 2

    for (int t = 0; t < TT; t++) {
        const int rp = t & 1, wp = rp ^ 1;

        // ---------------- phase 1 ----------------
        {
            const __half *A, *Bw;
            switch (cid) {
                case 0:  A = g_h1a[rp]; Bw = g_Whh1a; break;
                case 1:  A = g_h1m[rp]; Bw = g_Whh1m; break;
                case 2:  A = g_h2a;     Bw = g_Whh2a; break;
                default: A = g_h2m;     Bw = g_Whh2m; break;
            }
            float acc[4][4] = {};
            run_gemm_seq<128, 4, 5>(A, Bw, u0, dyn, acc);
            seq_store_sC<128, 4>(sC, acc);
            __syncthreads();

            if (cid < 2) {
                const float*  X1 = (cid == 0) ? g_X1a : g_X1m;
                float*        c_ = (cid == 0) ? g_c1a : g_c1m;
                __half*       h_ = (cid == 0) ? g_h1a[wp] : g_h1m[wp];
                for (int idx = threadIdx.x; idx < 32 * 32; idx += 256) {
                    int b = idx >> 5, j = idx & 31, u = u0 + j;
                    size_t xb = ((size_t)(b * 64 + t)) * G4 + u;
                    float i_ = sC[b * 128 + j]      + X1[xb];
                    float f_ = sC[b * 128 + 32 + j] + X1[xb + 1024];
                    float g_ = sC[b * 128 + 64 + j] + X1[xb + 2048];
                    float o_ = sC[b * 128 + 96 + j] + X1[xb + 3072];
                    float cn = sigf(f_) * c_[b * HD + u] + sigf(i_) * tanhf(g_);
                    c_[b * HD + u] = cn;
                    h_[b * HD + u] = __float2half_rn(sigf(o_) * tanhf(cn));
                }
            } else {
                float*       P  = (cid == 2) ? g_part2a : g_part2m;
                const float* bi = (cid == 2) ? g_bias2a : g_bias2m;
                for (int idx = threadIdx.x; idx < 32 * 128; idx += 256) {
                    int b = idx >> 7, n = idx & 127;
                    int col = ((n >> 5) << 10) + u0 + (n & 31);
                    P[b * G4 + col] = sC[b * 128 + n] + bi[col];
                }
            }
        }
        gsync(SEQ_CTAS);

        // ---------------- phase 2 ----------------
        {
            const __half* A2 = (cell == 0) ? g_h1a[wp] : g_h1m[wp];
            const __half* B2 = (cell == 0) ? g_Wih2a   : g_Wih2m;
            float acc2[2][4] = {};
            run_gemm_seq<64, 2, 4>(A2, B2, u0p, dyn, acc2);
            seq_store_sC<64, 2>(sC, acc2);
            __syncthreads();

            const float* P  = (cell == 0) ? g_part2a : g_part2m;
            float*       c_ = (cell == 0) ? g_c2a : g_c2m;
            __half*      h_ = (cell == 0) ? g_h2a : g_h2m;
            const int hoff  = (cell == 0) ? 0 : 1024;
            for (int idx = threadIdx.x; idx < 32 * 16; idx += 256) {
                int b = idx >> 4, j = idx & 15, u = u0p + j;
                size_t pb = (size_t)b * G4 + u;
                float i_ = sC[b * 64 + j]      + P[pb];
                float f_ = sC[b * 64 + 16 + j] + P[pb + 1024];
                float g_ = sC[b * 64 + 32 + j] + P[pb + 2048];
                float o_ = sC[b * 64 + 48 + j] + P[pb + 3072];
                float cn = sigf(f_) * c_[b * HD + u] + sigf(i_) * tanhf(g_);
                c_[b * HD + u] = cn;
                __half hv = __float2half_rn(sigf(o_) * tanhf(cn));
                h_[b * HD + u] = hv;
                g_Hcat[(size_t)(b * 64 + t) * 2048 + hoff + u] = hv;
            }
        }
        gsync(SEQ_CTAS);
    }
}

// ---------------- utility kernels ----------------
__global__ void __launch_bounds__(256) f2h_sel_kernel(const float4* __restrict__ src,
                                                      int which, int n4)
{
    __half* dst;
    switch (which) {
        case 0:  dst = g_Xa;    break;
        case 1:  dst = g_Xm;    break;
        case 2:  dst = g_Wih1a; break;
        case 3:  dst = g_Wih1m; break;
        case 4:  dst = g_Whh1a; break;
        case 5:  dst = g_Whh1m; break;
        case 6:  dst = g_Wih2a; break;
        case 7:  dst = g_Wih2m; break;
        case 8:  dst = g_Whh2a; break;
        case 9:  dst = g_Whh2m; break;
        case 10: dst = g_Wg;    break;
        case 11: dst = g_Wa;    break;
        default: dst = g_Wm;    break;
    }
    int i = blockIdx.x * 256 + threadIdx.x;
    if (i < n4) {
        float4 v = src[i];
        __half2 lo = __floats2half2_rn(v.x, v.y);
        __half2 hi = __floats2half2_rn(v.z, v.w);
        uint2 o;
        o.x = *reinterpret_cast<const uint32_t*>(&lo);
        o.y = *reinterpret_cast<const uint32_t*>(&hi);
        reinterpret_cast<uint2*>(dst)[i] = o;
    }
}

__global__ void __launch_bounds__(256) zero_state_kernel()
{
    int i = blockIdx.x * 256 + threadIdx.x;
    if (i < BB * HD) {
        g_h1a[0][i] = __half(0.f); g_h1a[1][i] = __half(0.f);
        g_h1m[0][i] = __half(0.f); g_h1m[1][i] = __half(0.f);
        g_h2a[i] = __half(0.f);    g_h2m[i] = __half(0.f);
        g_c1a[i] = 0.f; g_c1m[i] = 0.f; g_c2a[i] = 0.f; g_c2m[i] = 0.f;
    }
}

__global__ void __launch_bounds__(256) bias_kernel(
    const float* b1a, const float* b1a2, const float* b1m, const float* b1m2,
    const float* b2a, const float* b2a2, const float* b2m, const float* b2m2)
{
    int i = blockIdx.x * 256 + threadIdx.x;
    if (i < G4) {
        g_bias1a[i] = b1a[i] + b1a2[i];
        g_bias1m[i] = b1m[i] + b1m2[i];
        g_bias2a[i] = b2a[i] + b2a2[i];
        g_bias2m[i] = b2m[i] + b2m2[i];
    }
}

__global__ void __launch_bounds__(256) fuse_kernel(
    const float* __restrict__ bg, const float* __restrict__ ba,
    const float* __restrict__ bm, float* __restrict__ out)
{
    int i = blockIdx.x * 256 + threadIdx.x;
    if (i < BT * HD) {
        int h = i & 1023;
        float g = sigf(g_Gl[i] + bg[h]);
        out[i] = g * tanhf(g_Sa[i] + ba[h]) + (1.f - g) * tanhf(g_Sm[i] + bm[h]);
    }
}

// ---------------- host ----------------
extern "C" void kernel_launch(void* const* d_in, const int* in_sizes, int n_in,
                              void* d_out, int out_size)
{
    if (n_in < 24) return;
    const float* in[24];
    for (int i = 0; i < 24; i++) in[i] = (const float*)d_in[i];
    // 0 app, 1 mot, 2-5 1a(Wih,Whh,bih,bhh), 6-9 2a, 10-13 1m, 14-17 2m,
    // 18 Wg, 19 bg, 20 Wa, 21 ba, 22 Wm, 23 bm

    static bool attrs_set = false;
    if (!attrs_set) {
        cudaFuncSetAttribute(gemm_big, cudaFuncAttributeMaxDynamicSharedMemorySize, BIG_DYN);
        cudaFuncSetAttribute(seq_kernel, cudaFuncAttributeMaxDynamicSharedMemorySize, SEQ_DYN);
        attrs_set = true;
    }

    auto f2h = [&](int src, int which, int n) {
        int n4 = n / 4;
        f2h_sel_kernel<<<(n4 + 255) / 256, 256>>>((const float4*)in[src], which, n4);
    };

    // Order arranged so overall launch #6 (= my #4) is gemm_big(0).
    f2h(0, 0, BT * 2048);                                                  // 1 Xa
    f2h(2, 2, G4 * 2048);                                                  // 2 Wih1a
    bias_kernel<<<(G4 + 255) / 256, 256>>>(in[4], in[5], in[12], in[13],
                                           in[8], in[9], in[16], in[17]);  // 3
    gemm_big<<<dim3(32, 16), 256, BIG_DYN>>>(0);                           // 4 <- PROFILED

    f2h(1, 1, BT * 2048);    // Xm
    f2h(10, 3, G4 * 2048);   // Wih1m
    gemm_big<<<dim3(32, 16), 256, BIG_DYN>>>(1);

    f2h(3,  4, G4 * HD);     // Whh1a
    f2h(11, 5, G4 * HD);     // Whh1m
    f2h(6,  6, G4 * HD);     // Wih2a
    f2h(14, 7, G4 * HD);     // Wih2m
    f2h(7,  8, G4 * HD);     // Whh2a
    f2h(15, 9, G4 * HD);     // Whh2m
    f2h(18, 10, HD * 2048);  // Wg
    f2h(20, 11, HD * HD);    // Wa
    f2h(22, 12, HD * HD);    // Wm
    zero_state_kernel<<<(BB * HD + 255) / 256, 256>>>();

    // whole sequential recurrence in ONE persistent kernel
    seq_kernel<<<SEQ_CTAS, 256, SEQ_DYN>>>();

    // fusion GEMMs: M=2048, N=1024
    gemm_big<<<dim3(8, 16), 256, BIG_DYN>>>(4);
    gemm_big<<<dim3(8, 16), 256, BIG_DYN>>>(2);
    gemm_big<<<dim3(8, 16), 256, BIG_DYN>>>(3);

    fuse_kernel<<<(BT * HD + 255) / 256, 256>>>(in[19], in[21], in[23], (float*)d_out);
}

// round 13
// speedup vs baseline: 1.0183x; 1.0183x over previous
#include <cuda_runtime.h>
#include <cuda_fp16.h>
#include <cstdint>
#include <cstddef>

// B=32, T=64, H=1024. fp16 operands / fp32 accum everywhere.
#define HD 1024
#define BB 32
#define TT 64
#define G4 4096
#define BT 2048

// ---------------- static device buffers ----------------
__device__ __align__(1024) __half g_Xa   [BT * 2048];
__device__ __align__(1024) __half g_Xm   [BT * 2048];
__device__ __align__(1024) __half g_Wih1a[G4 * 2048];
__device__ __align__(1024) __half g_Wih1m[G4 * 2048];
__device__ __align__(1024) __half g_Whh1a[G4 * HD];
__device__ __align__(1024) __half g_Whh1m[G4 * HD];
__device__ __align__(1024) __half g_Wih2a[G4 * HD];
__device__ __align__(1024) __half g_Wih2m[G4 * HD];
__device__ __align__(1024) __half g_Whh2a[G4 * HD];
__device__ __align__(1024) __half g_Whh2m[G4 * HD];
__device__ __align__(1024) __half g_Wg   [HD * 2048];
__device__ __align__(1024) __half g_Wa   [HD * HD];
__device__ __align__(1024) __half g_Wm   [HD * HD];

__device__ __align__(1024) float  g_X1a[(size_t)BT * G4];
__device__ __align__(1024) float  g_X1m[(size_t)BT * G4];
__device__ float g_bias1a[G4], g_bias1m[G4], g_bias2a[G4], g_bias2m[G4];

__device__ __align__(1024) __half g_h1a[2][BB * HD];
__device__ __align__(1024) __half g_h1m[2][BB * HD];
__device__ __align__(1024) __half g_h2a[BB * HD];
__device__ __align__(1024) __half g_h2m[BB * HD];
__device__ __align__(1024) float  g_c1a[BB * HD], g_c1m[BB * HD];
__device__ __align__(1024) float  g_c2a[BB * HD], g_c2m[BB * HD];
__device__ __align__(1024) float  g_part2a[BB * G4], g_part2m[BB * G4];

__device__ __align__(1024) __half g_Hcat[BT * 2048];
__device__ __align__(1024) float  g_Sa[BT * HD], g_Sm[BT * HD], g_Gl[BT * HD];

// device-wide barrier state for the persistent sequential kernel
__device__ int          g_bar_count = 0;
__device__ volatile int g_bar_gen   = 0;

// ---------------- helpers ----------------
__device__ __forceinline__ float sigf(float x) { return 1.f / (1.f + expf(-x)); }

__device__ __forceinline__ void cp8(void* s, const void* g) {
    uint32_t sa = (uint32_t)__cvta_generic_to_shared(s);
    asm volatile("cp.async.ca.shared.global [%0], [%1], 8;" :: "r"(sa), "l"(g));
}

__device__ __forceinline__ void mma16816(float* d, const uint32_t* a, const uint32_t* b) {
    asm volatile(
        "mma.sync.aligned.m16n8k16.row.col.f32.f16.f16.f32 "
        "{%0,%1,%2,%3}, {%4,%5,%6,%7}, {%8,%9}, {%0,%1,%2,%3};"
        : "+f"(d[0]), "+f"(d[1]), "+f"(d[2]), "+f"(d[3])
        : "r"(a[0]), "r"(a[1]), "r"(a[2]), "r"(a[3]), "r"(b[0]), "r"(b[1]));
}

// exact tail-laddered wait: group kt must be complete
__device__ __forceinline__ void wait_tail(int kt, int KT) {
    if (kt + 3 < KT)      asm volatile("cp.async.wait_group 3;" ::: "memory");
    else if (kt + 2 < KT) asm volatile("cp.async.wait_group 2;" ::: "memory");
    else if (kt + 1 < KT) asm volatile("cp.async.wait_group 1;" ::: "memory");
    else                  asm volatile("cp.async.wait_group 0;" ::: "memory");
}

// all-CTA barrier (all CTAs resident: grid=128 <= 148 SMs), tight spin
__device__ __forceinline__ void gsync(int nblocks) {
    __syncthreads();
    if (threadIdx.x == 0) {
        int gen = g_bar_gen;
        __threadfence();
        if (atomicAdd(&g_bar_count, 1) == nblocks - 1) {
            g_bar_count = 0;
            __threadfence();
            g_bar_gen = gen + 1;
        } else {
            while (g_bar_gen == gen) { }
        }
        __threadfence();
    }
    __syncthreads();
}

// ---------------- big GEMM: 4-stage cp.async pipeline -----------------------
#define BKC 32
#define SK  40
#define SKW 20
#define BIG_STAGE_BYTES (256 * SK * 2)
#define BIG_DYN (4 * BIG_STAGE_BYTES)

__global__ void __launch_bounds__(256) gemm_big(int which)
{
    extern __shared__ __align__(16) char dyn[];

    const __half *A, *Bw;
    float* C;
    const float* bias = nullptr;
    int lda, ldb, K, ldc;
    const int n0 = blockIdx.x * 128, m0 = blockIdx.y * 128;
    switch (which) {
        case 0: A = g_Xa;        lda = 2048; Bw = g_Wih1a; ldb = 2048; K = 2048; C = g_X1a; ldc = G4; bias = g_bias1a; break;
        case 1: A = g_Xm;        lda = 2048; Bw = g_Wih1m; ldb = 2048; K = 2048; C = g_X1m; ldc = G4; bias = g_bias1m; break;
        case 2: A = g_Hcat;      lda = 2048; Bw = g_Wa;    ldb = HD;   K = HD;   C = g_Sa;  ldc = HD; break;
        case 3: A = g_Hcat + HD; lda = 2048; Bw = g_Wm;    ldb = HD;   K = HD;   C = g_Sm;  ldc = HD; break;
        default:A = g_Hcat;      lda = 2048; Bw = g_Wg;    ldb = 2048; K = 2048; C = g_Gl;  ldc = HD; break;
    }
    A += (size_t)m0 * lda;

    const int tid  = threadIdx.x;
    const int warp = tid >> 5, lane = tid & 31;
    const int wm = warp >> 2, wn = warp & 3;
    const int grp = lane >> 2, tig = lane & 3;

    auto load_tile = [&](int kt) {
        char* st = dyn + (kt & 3) * BIG_STAGE_BYTES;
        __half* sa = (__half*)st;
        __half* sb = (__half*)(st + 128 * SK * 2);
        const __half* Ag = A + kt * BKC;
        const __half* Bg = Bw + kt * BKC;
        for (int idx = tid; idx < 2048; idx += 256) {
            int r = (idx >> 3) & 127, c = idx & 7;
            if (idx < 1024)
                cp8(sa + r * SK + c * 4, Ag + (size_t)r * lda + c * 4);
            else
                cp8(sb + r * SK + c * 4, Bg + (size_t)(n0 + r) * ldb + c * 4);
        }
        asm volatile("cp.async.commit_group;" ::: "memory");
    };

    float acc[16][4] = {};
    const int KT = K / BKC;
    load_tile(0); load_tile(1); load_tile(2);

    for (int kt = 0; kt < KT; kt++) {
        if (kt + 3 < KT) load_tile(kt + 3);
        wait_tail(kt, KT);
        __syncthreads();
        char* st = dyn + (kt & 3) * BIG_STAGE_BYTES;
        const uint32_t* wA = (const uint32_t*)st;
        const uint32_t* wB = (const uint32_t*)(st + 128 * SK * 2);
        #pragma unroll
        for (int kk = 0; kk < 2; kk++) {
            uint32_t af[4][4], bf[4][2];
            #pragma unroll
            for (int mi = 0; mi < 4; mi++) {
                int r = wm * 64 + mi * 16 + grp;
                int base = r * SKW + kk * 8 + tig;
                af[mi][0] = wA[base];
                af[mi][1] = wA[base + 8 * SKW];
                af[mi][2] = wA[base + 4];
                af[mi][3] = wA[base + 8 * SKW + 4];
            }
            #pragma unroll
            for (int ni = 0; ni < 4; ni++) {
                int rb = wn * 32 + ni * 8 + grp;
                int base = rb * SKW + kk * 8 + tig;
                bf[ni][0] = wB[base];
                bf[ni][1] = wB[base + 4];
            }
            #pragma unroll
            for (int mi = 0; mi < 4; mi++)
                #pragma unroll
                for (int ni = 0; ni < 4; ni++)
                    mma16816(acc[mi * 4 + ni], af[mi], bf[ni]);
        }
        __syncthreads();
    }

    #pragma unroll
    for (int mi = 0; mi < 4; mi++)
        #pragma unroll
        for (int ni = 0; ni < 4; ni++) {
            int r = m0 + wm * 64 + mi * 16 + grp;
            int c = n0 + wn * 32 + ni * 8 + tig * 2;
            float b0 = 0.f, b1 = 0.f;
            if (bias) { b0 = bias[c]; b1 = bias[c + 1]; }
            float* p = C + (size_t)r * ldc + c;
            p[0] = acc[mi * 4 + ni][0] + b0;
            p[1] = acc[mi * 4 + ni][1] + b1;
            p = C + (size_t)(r + 8) * ldc + c;
            p[0] = acc[mi * 4 + ni][2] + b0;
            p[1] = acc[mi * 4 + ni][3] + b1;
        }
}

// ---------------- sequential-core GEMM: 4-stage, BM=32, BN {128,64}, BK=64 --
#define BK2  64
#define SK2  72
#define SK2W 36
#define SEQ_STAGE_BYTES (160 * SK2 * 2)
#define SEQ_DYN (4 * SEQ_STAGE_BYTES)
#define SEQ_CTAS 128

template<int BN, int NI, int GS>
__device__ __forceinline__ void run_gemm_seq(
    const __half* __restrict__ A,
    const __half* __restrict__ Bw, int u0,
    char* dyn, float (*acc)[4])
{
    const int tid  = threadIdx.x;
    const int warp = tid >> 5, lane = tid & 31;
    const int wm = warp >> 2, wn = warp & 3;
    const int grp = lane >> 2, tig = lane & 3;

    constexpr int TOT = 512 + BN * 16;

    auto load_tile = [&](int kt) {
        const int k0 = kt * BK2;
        char* st = dyn + (kt & 3) * SEQ_STAGE_BYTES;
        __half* sa = (__half*)st;
        __half* sb = (__half*)(st + 32 * SK2 * 2);
        for (int idx = tid; idx < TOT; idx += 256) {
            if (idx < 512) {
                int r = idx >> 4, c = idx & 15;
                cp8(sa + r * SK2 + c * 4, A + (size_t)r * HD + k0 + c * 4);
            } else {
                int j = idx - 512;
                int r = j >> 4, c = j & 15;
                int wr = ((r >> GS) << 10) + u0 + (r & ((1 << GS) - 1));
                cp8(sb + r * SK2 + c * 4, Bw + (size_t)wr * HD + k0 + c * 4);
            }
        }
        asm volatile("cp.async.commit_group;" ::: "memory");
    };

    const int KT = HD / BK2;   // 16
    load_tile(0); load_tile(1); load_tile(2);

    for (int kt = 0; kt < KT; kt++) {
        if (kt + 3 < KT) load_tile(kt + 3);
        wait_tail(kt, KT);
        __syncthreads();
        char* st = dyn + (kt & 3) * SEQ_STAGE_BYTES;
        const uint32_t* wA = (const uint32_t*)st;
        const uint32_t* wB = (const uint32_t*)(st + 32 * SK2 * 2);
        #pragma unroll
        for (int kk = 0; kk < 4; kk++) {
            uint32_t af[4], bf[NI][2];
            {
                int r = wm * 16 + grp;
                int base = r * SK2W + kk * 8 + tig;
                af[0] = wA[base];
                af[1] = wA[base + 8 * SK2W];
                af[2] = wA[base + 4];
                af[3] = wA[base + 8 * SK2W + 4];
            }
            #pragma unroll
            for (int ni = 0; ni < NI; ni++) {
                int rb = wn * (NI * 8) + ni * 8 + grp;
                int base = rb * SK2W + kk * 8 + tig;
                bf[ni][0] = wB[base];
                bf[ni][1] = wB[base + 4];
            }
            #pragma unroll
            for (int ni = 0; ni < NI; ni++)
                mma16816(acc[ni], af, bf[ni]);
        }
        __syncthreads();
    }
}

template<int BN, int NI>
__device__ __forceinline__ void seq_store_sC(float* sC, float (*acc)[4])
{
    const int warp = threadIdx.x >> 5, lane = threadIdx.x & 31;
    const int wm = warp >> 2, wn = warp & 3, grp = lane >> 2, tig = lane & 3;
    #pragma unroll
    for (int ni = 0; ni < NI; ni++) {
        int r = wm * 16 + grp, c = wn * (NI * 8) + ni * 8 + tig * 2;
        sC[r * BN + c]           = acc[ni][0];  sC[r * BN + c + 1]       = acc[ni][1];
        sC[(r + 8) * BN + c]     = acc[ni][2];  sC[(r + 8) * BN + c + 1] = acc[ni][3];
    }
}

// ---------------- persistent sequential kernel (grid = 128 CTAs) ------------
__global__ void __launch_bounds__(256) seq_kernel()
{
    extern __shared__ __align__(16) char dyn[];
    float* sC = (float*)dyn;

    const int bx   = blockIdx.x;
    const int cid  = bx >> 5, u0  = (bx & 31) << 5;   // phase 1
    const int cell = bx >> 6, u0p = (bx & 63) << 4;   // phase 2

    for (int t = 0; t < TT; t++) {
        const int rp = t & 1, wp = rp ^ 1;

        // ---------------- phase 1 ----------------
        {
            const __half *A, *Bw;
            switch (cid) {
                case 0:  A = g_h1a[rp]; Bw = g_Whh1a; break;
                case 1:  A = g_h1m[rp]; Bw = g_Whh1m; break;
                case 2:  A = g_h2a;     Bw = g_Whh2a; break;
                default: A = g_h2m;     Bw = g_Whh2m; break;
            }
            float acc[4][4] = {};
            run_gemm_seq<128, 4, 5>(A, Bw, u0, dyn, acc);
            seq_store_sC<128, 4>(sC, acc);
            __syncthreads();

            if (cid < 2) {
                const float*  X1 = (cid == 0) ? g_X1a : g_X1m;
                float*        c_ = (cid == 0) ? g_c1a : g_c1m;
                __half*       h_ = (cid == 0) ? g_h1a[wp] : g_h1m[wp];
                for (int idx = threadIdx.x; idx < 32 * 32; idx += 256) {
                    int b = idx >> 5, j = idx & 31, u = u0 + j;
                    size_t xb = ((size_t)(b * 64 + t)) * G4 + u;
                    float i_ = sC[b * 128 + j]      + X1[xb];
                    float f_ = sC[b * 128 + 32 + j] + X1[xb + 1024];
                    float g_ = sC[b * 128 + 64 + j] + X1[xb + 2048];
                    float o_ = sC[b * 128 + 96 + j] + X1[xb + 3072];
                    float cn = sigf(f_) * c_[b * HD + u] + sigf(i_) * tanhf(g_);
                    c_[b * HD + u] = cn;
                    h_[b * HD + u] = __float2half_rn(sigf(o_) * tanhf(cn));
                }
            } else {
                float*       P  = (cid == 2) ? g_part2a : g_part2m;
                const float* bi = (cid == 2) ? g_bias2a : g_bias2m;
                for (int idx = threadIdx.x; idx < 32 * 128; idx += 256) {
                    int b = idx >> 7, n = idx & 127;
                    int col = ((n >> 5) << 10) + u0 + (n & 31);
                    P[b * G4 + col] = sC[b * 128 + n] + bi[col];
                }
            }
        }
        gsync(SEQ_CTAS);

        // ---------------- phase 2 ----------------
        {
            const __half* A2 = (cell == 0) ? g_h1a[wp] : g_h1m[wp];
            const __half* B2 = (cell == 0) ? g_Wih2a   : g_Wih2m;
            float acc2[2][4] = {};
            run_gemm_seq<64, 2, 4>(A2, B2, u0p, dyn, acc2);
            seq_store_sC<64, 2>(sC, acc2);
            __syncthreads();

            const float* P  = (cell == 0) ? g_part2a : g_part2m;
            float*       c_ = (cell == 0) ? g_c2a : g_c2m;
            __half*      h_ = (cell == 0) ? g_h2a : g_h2m;
            const int hoff  = (cell == 0) ? 0 : 1024;
            for (int idx = threadIdx.x; idx < 32 * 16; idx += 256) {
                int b = idx >> 4, j = idx & 15, u = u0p + j;
                size_t pb = (size_t)b * G4 + u;
                float i_ = sC[b * 64 + j]      + P[pb];
                float f_ = sC[b * 64 + 16 + j] + P[pb + 1024];
                float g_ = sC[b * 64 + 32 + j] + P[pb + 2048];
                float o_ = sC[b * 64 + 48 + j] + P[pb + 3072];
                float cn = sigf(f_) * c_[b * HD + u] + sigf(i_) * tanhf(g_);
                c_[b * HD + u] = cn;
                __half hv = __float2half_rn(sigf(o_) * tanhf(cn));
                h_[b * HD + u] = hv;
                g_Hcat[(size_t)(b * 64 + t) * 2048 + hoff + u] = hv;
            }
        }
        gsync(SEQ_CTAS);
    }
}

// ---------------- single conversion kernel (all f2h + bias + zero) ----------
struct Ptrs { const float* p[24]; };

// segment block offsets (256 threads each, f4 units)
#define SEG0  0        // Xa     4096
#define SEG1  4096     // Xm     4096
#define SEG2  8192     // Wih1a  8192
#define SEG3  16384    // Wih1m  8192
#define SEG4  24576    // Whh1a  4096
#define SEG5  28672    // Whh1m  4096
#define SEG6  32768    // Wih2a  4096
#define SEG7  36864    // Wih2m  4096
#define SEG8  40960    // Whh2a  4096
#define SEG9  45056    // Whh2m  4096
#define SEG10 49152    // Wg     2048
#define SEG11 51200    // Wa     1024
#define SEG12 52224    // Wm     1024
#define SEG13 53248    // bias   16
#define SEG14 53264    // zero   128
#define SEG_TOTAL 53392

__global__ void __launch_bounds__(256) convert_all(Ptrs P)
{
    const int b = blockIdx.x;
    const int t = threadIdx.x;

    auto conv = [&](const float* s, __half* d, int blk0) {
        int i = (b - blk0) * 256 + t;
        float4 v = ((const float4*)s)[i];
        __half2 lo = __floats2half2_rn(v.x, v.y);
        __half2 hi = __floats2half2_rn(v.z, v.w);
        uint2 o;
        o.x = *reinterpret_cast<const uint32_t*>(&lo);
        o.y = *reinterpret_cast<const uint32_t*>(&hi);
        ((uint2*)d)[i] = o;
    };

    if      (b < SEG1)  conv(P.p[0],  g_Xa,    SEG0);
    else if (b < SEG2)  conv(P.p[1],  g_Xm,    SEG1);
    else if (b < SEG3)  conv(P.p[2],  g_Wih1a, SEG2);
    else if (b < SEG4)  conv(P.p[10], g_Wih1m, SEG3);
    else if (b < SEG5)  conv(P.p[3],  g_Whh1a, SEG4);
    else if (b < SEG6)  conv(P.p[11], g_Whh1m, SEG5);
    else if (b < SEG7)  conv(P.p[6],  g_Wih2a, SEG6);
    else if (b < SEG8)  conv(P.p[14], g_Wih2m, SEG7);
    else if (b < SEG9)  conv(P.p[7],  g_Whh2a, SEG8);
    else if (b < SEG10) conv(P.p[15], g_Whh2m, SEG9);
    else if (b < SEG11) conv(P.p[18], g_Wg,    SEG10);
    else if (b < SEG12) conv(P.p[20], g_Wa,    SEG11);
    else if (b < SEG13) conv(P.p[22], g_Wm,    SEG12);
    else if (b < SEG14) {
        int i = (b - SEG13) * 256 + t;
        g_bias1a[i] = P.p[4][i]  + P.p[5][i];
        g_bias1m[i] = P.p[12][i] + P.p[13][i];
        g_bias2a[i] = P.p[8][i]  + P.p[9][i];
        g_bias2m[i] = P.p[16][i] + P.p[17][i];
    } else {
        int i = (b - SEG14) * 256 + t;
        g_h1a[0][i] = __half(0.f); g_h1a[1][i] = __half(0.f);
        g_h1m[0][i] = __half(0.f); g_h1m[1][i] = __half(0.f);
        g_h2a[i] = __half(0.f);    g_h2m[i] = __half(0.f);
        g_c1a[i] = 0.f; g_c1m[i] = 0.f; g_c2a[i] = 0.f; g_c2m[i] = 0.f;
    }
}

// ---------------- fuse ----------------
__global__ void __launch_bounds__(256) fuse_kernel(
    const float* __restrict__ bg, const float* __restrict__ ba,
    const float* __restrict__ bm, float* __restrict__ out)
{
    int i = blockIdx.x * 256 + threadIdx.x;
    if (i < BT * HD) {
        int h = i & 1023;
        float g = sigf(g_Gl[i] + bg[h]);
        out[i] = g * tanhf(g_Sa[i] + ba[h]) + (1.f - g) * tanhf(g_Sm[i] + bm[h]);
    }
}

// ---------------- host ----------------
extern "C" void kernel_launch(void* const* d_in, const int* in_sizes, int n_in,
                              void* d_out, int out_size)
{
    if (n_in < 24) return;
    Ptrs P;
    for (int i = 0; i < 24; i++) P.p[i] = (const float*)d_in[i];
    // 0 app, 1 mot, 2-5 1a(Wih,Whh,bih,bhh), 6-9 2a, 10-13 1m, 14-17 2m,
    // 18 Wg, 19 bg, 20 Wa, 21 ba, 22 Wm, 23 bm

    static bool attrs_set = false;
    if (!attrs_set) {
        cudaFuncSetAttribute(gemm_big, cudaFuncAttributeMaxDynamicSharedMemorySize, BIG_DYN);
        cudaFuncSetAttribute(seq_kernel, cudaFuncAttributeMaxDynamicSharedMemorySize, SEQ_DYN);
        attrs_set = true;
    }

    // Launch order: my #4 (= overall #6 incl. 2 harness launches) is seq_kernel -> PROFILED.
    convert_all<<<SEG_TOTAL, 256>>>(P);                 // 1: all f2h + bias + zero
    gemm_big<<<dim3(32, 16), 256, BIG_DYN>>>(0);        // 2: X1a
    gemm_big<<<dim3(32, 16), 256, BIG_DYN>>>(1);        // 3: X1m
    seq_kernel<<<SEQ_CTAS, 256, SEQ_DYN>>>();           // 4: <- PROFILED

    gemm_big<<<dim3(8, 16), 256, BIG_DYN>>>(4);         // Gl
    gemm_big<<<dim3(8, 16), 256, BIG_DYN>>>(2);         // Sa
    gemm_big<<<dim3(8, 16), 256, BIG_DYN>>>(3);         // Sm

    fuse_kernel<<<(BT * HD + 255) / 256, 256>>>(P.p[19], P.p[21], P.p[23], (float*)d_out);
}